// round 5
// baseline (speedup 1.0000x reference)
#include <cuda_runtime.h>
#include <cuda_bf16.h>
#include <cstdint>

// ---------------- problem constants ----------------
#define NPMAX   2400000
#define GX      432
#define GY      496
#define NVOX    (GX*GY)        // 214272 (z dim = 1)
#define MAXV    40000
#define MAXP    32
#define CAP     64             // per-voxel bucket capacity (P(count>64) ~ e^-60)
#define SENTINEL 0x7FFFFFFF

// ---------------- device scratch (static: no allocations allowed) ----------------
__device__ int g_first[NVOX];       // min original point index per voxel
__device__ int g_cnt[NVOX];         // total arrivals per voxel
__device__ int g_vlist[MAXV];       // slot -> voxel lin id (-1 = unassigned)
__device__ int g_vbuf[NVOX * CAP];  // per-voxel point indices (unordered set), ~55 MB, L2-resident

// ---------------- voxel coordinate ----------------
// Mirror of what XLA actually computes for (p - pc_min) / voxel_size:
// the AlgebraicSimplifier turns div-by-constant into mul-by-RN(1/const).
// RN(1/0.16f) = 6.25f exactly; RN(1/4.0f) = 0.25f.  Intrinsics prevent
// FMA contraction so the sub and mul round separately, like XLA's HLO.
__device__ __forceinline__ int point_lin(float4 p) {
    float fx = floorf(__fmul_rn(__fsub_rn(p.x,   0.0f), 6.25f));
    float fy = floorf(__fmul_rn(__fsub_rn(p.y, -39.68f), 6.25f));
    float fz = floorf(__fmul_rn(__fsub_rn(p.z,  -3.0f), 0.25f));
    bool valid = (fx >= 0.f) & (fx < (float)GX) &
                 (fy >= 0.f) & (fy < (float)GY) &
                 (fz >= 0.f) & (fz < 1.f);
    if (!valid) return -1;
    return (int)fy * GX + (int)fx;   // z == 0
}

// ---------------- kernels ----------------
__global__ void k_init(float* __restrict__ o_coor) {
    int i = blockIdx.x * blockDim.x + threadIdx.x;
    if (i < NVOX) { g_first[i] = SENTINEL; g_cnt[i] = 0; }
    if (i < MAXV)  g_vlist[i] = -1;
    if (i < MAXV * 3) o_coor[i] = -1.0f;
}

__global__ void k_point(const float4* __restrict__ pts, int n) {
    int i = blockIdx.x * blockDim.x + threadIdx.x;
    if (i >= n) return;
    int lin = point_lin(pts[i]);
    if (lin < 0) return;
    atomicMin(&g_first[lin], i);
    int j = atomicAdd(&g_cnt[lin], 1);
    if (j < CAP) g_vbuf[lin * CAP + j] = i;   // unordered set; order fixed later by rank
}

// Single block, 1024 threads. Sequentially scans points in index order, assigns
// output slots to voxel-first points (rank = slot), stops once MAXV slots are
// assigned. Fully deterministic: plain ordered scan, no atomics.
__global__ void k_order(const float4* __restrict__ pts, int n,
                        float* __restrict__ o_coor) {
    __shared__ int sh[1024];
    __shared__ int s_off;
    int tid = threadIdx.x;
    if (tid == 0) s_off = 0;
    __syncthreads();

    for (int base = 0; base < n; base += 4096) {
        // each thread: 4 consecutive points
        int i0 = base + tid * 4;
        int lin[4], m[4];
        #pragma unroll
        for (int k = 0; k < 4; k++) {
            int i = i0 + k;
            int l = (i < n) ? point_lin(pts[i]) : -1;
            lin[k] = l;
            m[k] = (l >= 0 && g_first[l] == i) ? 1 : 0;
        }
        int s = m[0] + m[1] + m[2] + m[3];

        // block-wide Hillis-Steele inclusive scan of per-thread sums
        sh[tid] = s;
        __syncthreads();
        for (int o = 1; o < 1024; o <<= 1) {
            int t = (tid >= o) ? sh[tid - o] : 0;
            __syncthreads();
            sh[tid] += t;
            __syncthreads();
        }
        int excl  = sh[tid] - s;     // exclusive prefix for this thread
        int total = sh[1023];        // chunk total

        int r = s_off + excl;
        #pragma unroll
        for (int k = 0; k < 4; k++) {
            if (m[k]) {
                if (r < MAXV) {
                    g_vlist[r] = lin[k];
                    int x = lin[k] % GX, y = lin[k] / GX;   // z == 0
                    o_coor[r * 3 + 0] = 0.0f;
                    o_coor[r * 3 + 1] = (float)y;
                    o_coor[r * 3 + 2] = (float)x;
                }
                r++;
            }
        }
        __syncthreads();             // all uses of s_off/sh done
        if (tid == 0) s_off += total;
        __syncthreads();
        if (s_off >= MAXV) break;    // uniform: all slots assigned (~11 chunks here)
    }
}

// One warp per slot: rank its <=64 bucket entries by original point index
// (distinct indices -> ranks are a permutation), keep ranks < 32.
__global__ void k_emit(const float4* __restrict__ pts,
                       float4* __restrict__ o_vox,
                       float* __restrict__ o_np) {
    int s = blockIdx.x * 8 + (threadIdx.x >> 5);
    if (s >= MAXV) return;
    int lane = threadIdx.x & 31;
    int lin = g_vlist[s];
    int n = (lin >= 0) ? g_cnt[lin] : 0;
    if (lane == 0) o_np[s] = (float)min(n, MAXP);
    if (n == 0) return;
    int m = min(n, CAP);
    const int* buf = &g_vbuf[lin * CAP];
    int e0 = (lane      < m) ? buf[lane]      : SENTINEL;
    int e1 = (lane + 32 < m) ? buf[lane + 32] : SENTINEL;
    int r0 = 0, r1 = 0;
    #pragma unroll
    for (int j = 0; j < 32; j++) {
        int a = __shfl_sync(0xffffffffu, e0, j);
        int b = __shfl_sync(0xffffffffu, e1, j);
        r0 += (a < e0) + (b < e0);
        r1 += (a < e1) + (b < e1);
    }
    if (e0 != SENTINEL && r0 < MAXP) o_vox[(size_t)s * MAXP + r0] = pts[e0];
    if (e1 != SENTINEL && r1 < MAXP) o_vox[(size_t)s * MAXP + r1] = pts[e1];
}

// ---------------- launch ----------------
extern "C" void kernel_launch(void* const* d_in, const int* in_sizes, int n_in,
                              void* d_out, int out_size) {
    const float4* pts = (const float4*)d_in[0];
    int n = in_sizes[0] / 4;
    if (n > NPMAX) n = NPMAX;

    float* out    = (float*)d_out;
    float* o_coor = out + (size_t)MAXV * MAXP * 4;   // 5,120,000
    float* o_np   = o_coor + (size_t)MAXV * 3;       // +120,000

    cudaMemsetAsync(d_out, 0, (size_t)out_size * sizeof(float), 0);

    k_init <<<(NVOX + 255) / 256, 256>>>(o_coor);
    k_point<<<(n + 255) / 256, 256>>>(pts, n);
    k_order<<<1, 1024>>>(pts, n, o_coor);
    k_emit <<<(MAXV + 7) / 8, 256>>>(pts, (float4*)out, o_np);
}

// round 6
// speedup vs baseline: 1.6042x; 1.6042x over previous
#include <cuda_runtime.h>
#include <cuda_bf16.h>
#include <cstdint>

// ---------------- problem constants ----------------
#define NPMAX   2400000
#define GX      432
#define GY      496
#define NVOX    (GX*GY)        // 214272 (z dim = 1)
#define MAXV    40000
#define MAXP    32
#define CAP     64             // per-voxel bucket capacity (P(count>64) ~ e^-60)
#define CHUNK   4096           // points per block in ranking passes
#define SENTINEL 0x7FFFFFFF

// ---------------- device scratch (static: no allocations allowed) ----------------
__device__ int g_first[NVOX];       // min original point index per voxel
__device__ int g_cnt[NVOX];         // total arrivals per voxel
__device__ int g_lin[NPMAX];        // cached voxel id per point (-1 invalid)
__device__ int g_vlist[MAXV];       // slot -> voxel lin id (-1 = unassigned)
__device__ int g_vbuf[NVOX * CAP];  // per-voxel point indices (unordered set), ~55 MB, L2-resident
__device__ int g_bsum[1024];        // per-block first-point counts -> exclusive scanned

// ---------------- voxel coordinate ----------------
// Mirror of what XLA actually computes for (p - pc_min) / voxel_size:
// div-by-constant is rewritten to mul-by-RN(1/const). RN(1/0.16f) = 6.25f
// exactly; RN(1/4.0f) = 0.25f. Intrinsics block FMA contraction so sub and
// mul round separately, like the HLO. (Verified bit-exact in Round 5.)
__device__ __forceinline__ int point_lin(float4 p) {
    float fx = floorf(__fmul_rn(__fsub_rn(p.x,   0.0f), 6.25f));
    float fy = floorf(__fmul_rn(__fsub_rn(p.y, -39.68f), 6.25f));
    float fz = floorf(__fmul_rn(__fsub_rn(p.z,  -3.0f), 0.25f));
    bool valid = (fx >= 0.f) & (fx < (float)GX) &
                 (fy >= 0.f) & (fy < (float)GY) &
                 (fz >= 0.f) & (fz < 1.f);
    if (!valid) return -1;
    return (int)fy * GX + (int)fx;   // z == 0
}

// ---------------- kernels ----------------
__global__ void k_init(float* __restrict__ o_coor) {
    int i = blockIdx.x * blockDim.x + threadIdx.x;
    if (i < NVOX) { g_first[i] = SENTINEL; g_cnt[i] = 0; }
    if (i < MAXV)  g_vlist[i] = -1;
    if (i < MAXV * 3) o_coor[i] = -1.0f;
}

__global__ void k_point(const float4* __restrict__ pts, int n) {
    int i = blockIdx.x * blockDim.x + threadIdx.x;
    if (i >= n) return;
    int lin = point_lin(pts[i]);
    g_lin[i] = lin;
    if (lin < 0) return;
    atomicMin(&g_first[lin], i);
    int j = atomicAdd(&g_cnt[lin], 1);
    if (j < CAP) g_vbuf[lin * CAP + j] = i;   // unordered set; order fixed later by rank
}

// Per-block count of first-occurrence points. 1024 threads, 4 points each.
__global__ void k_sums(int n) {
    __shared__ int red[32];
    int base = blockIdx.x * CHUNK + threadIdx.x * 4;
    int s = 0;
    #pragma unroll
    for (int k = 0; k < 4; k++) {
        int i = base + k;
        if (i < n) {
            int l = g_lin[i];
            s += (l >= 0 && g_first[l] == i) ? 1 : 0;
        }
    }
    int lane = threadIdx.x & 31, w = threadIdx.x >> 5;
    #pragma unroll
    for (int o = 16; o > 0; o >>= 1) s += __shfl_down_sync(0xffffffffu, s, o);
    if (lane == 0) red[w] = s;
    __syncthreads();
    if (w == 0) {
        int t = (lane < 32) ? red[lane] : 0;
        #pragma unroll
        for (int o = 16; o > 0; o >>= 1) t += __shfl_down_sync(0xffffffffu, t, o);
        if (lane == 0) g_bsum[blockIdx.x] = t;
    }
}

// Exclusive scan of g_bsum[0..nb), nb <= 1024, single block.
__global__ void k_scan(int nb) {
    __shared__ int sh[1024];
    int tid = threadIdx.x;
    int v = (tid < nb) ? g_bsum[tid] : 0;
    sh[tid] = v;
    __syncthreads();
    for (int o = 1; o < 1024; o <<= 1) {
        int t = (tid >= o) ? sh[tid - o] : 0;
        __syncthreads();
        sh[tid] += t;
        __syncthreads();
    }
    if (tid < nb) g_bsum[tid] = sh[tid] - v;   // exclusive
}

// Assign slots: block-local scan of marks + scanned block offset.
// Blocks entirely past MAXV slots exit immediately (~98% of blocks).
__global__ void k_rank(int n, float* __restrict__ o_coor) {
    int off = g_bsum[blockIdx.x];
    if (off >= MAXV) return;

    __shared__ int sh[1024];
    int tid = threadIdx.x;
    int base = blockIdx.x * CHUNK + tid * 4;

    int lin[4], m[4];
    int s = 0;
    #pragma unroll
    for (int k = 0; k < 4; k++) {
        int i = base + k;
        int l = (i < n) ? g_lin[i] : -1;
        lin[k] = l;
        m[k] = (l >= 0 && g_first[l] == i) ? 1 : 0;
        s += m[k];
    }

    sh[tid] = s;
    __syncthreads();
    for (int o = 1; o < 1024; o <<= 1) {
        int t = (tid >= o) ? sh[tid - o] : 0;
        __syncthreads();
        sh[tid] += t;
        __syncthreads();
    }
    int r = off + sh[tid] - s;   // global exclusive rank of this thread's first mark

    #pragma unroll
    for (int k = 0; k < 4; k++) {
        if (m[k]) {
            if (r < MAXV) {
                g_vlist[r] = lin[k];
                int x = lin[k] % GX, y = lin[k] / GX;   // z == 0
                o_coor[r * 3 + 0] = 0.0f;
                o_coor[r * 3 + 1] = (float)y;
                o_coor[r * 3 + 2] = (float)x;
            }
            r++;
        }
    }
}

// One warp per slot: rank its bucket entries by original point index
// (distinct indices -> ranks are a permutation), keep ranks < 32.
// Fast path (n <= 32, ~always): single lane value, loop bounded by m.
__global__ void k_emit(const float4* __restrict__ pts,
                       float4* __restrict__ o_vox,
                       float* __restrict__ o_np) {
    int s = blockIdx.x * 8 + (threadIdx.x >> 5);
    if (s >= MAXV) return;
    int lane = threadIdx.x & 31;
    int lin = g_vlist[s];
    int n = (lin >= 0) ? g_cnt[lin] : 0;
    if (lane == 0) o_np[s] = (float)min(n, MAXP);
    if (n == 0) return;
    const int* buf = &g_vbuf[lin * CAP];

    if (n <= 32) {                       // common case: loop only over m entries
        int m = n;
        int e0 = (lane < m) ? buf[lane] : SENTINEL;
        int r0 = 0;
        for (int j = 0; j < m; j++) {    // m uniform across the warp
            int a = __shfl_sync(0xffffffffu, e0, j);
            r0 += (a < e0) ? 1 : 0;
        }
        if (lane < m) o_vox[(size_t)s * MAXP + r0] = pts[e0];
    } else {                             // rare: up to 64 entries, keep ranks < 32
        int m = min(n, CAP);
        int e0 = (lane      < m) ? buf[lane]      : SENTINEL;
        int e1 = (lane + 32 < m) ? buf[lane + 32] : SENTINEL;
        int r0 = 0, r1 = 0;
        #pragma unroll
        for (int j = 0; j < 32; j++) {
            int a = __shfl_sync(0xffffffffu, e0, j);
            int b = __shfl_sync(0xffffffffu, e1, j);
            r0 += (a < e0) + (b < e0);
            r1 += (a < e1) + (b < e1);
        }
        if (e0 != SENTINEL && r0 < MAXP) o_vox[(size_t)s * MAXP + r0] = pts[e0];
        if (e1 != SENTINEL && r1 < MAXP) o_vox[(size_t)s * MAXP + r1] = pts[e1];
    }
}

// ---------------- launch ----------------
extern "C" void kernel_launch(void* const* d_in, const int* in_sizes, int n_in,
                              void* d_out, int out_size) {
    const float4* pts = (const float4*)d_in[0];
    int n = in_sizes[0] / 4;
    if (n > NPMAX) n = NPMAX;

    float* out    = (float*)d_out;
    float* o_coor = out + (size_t)MAXV * MAXP * 4;   // 5,120,000
    float* o_np   = o_coor + (size_t)MAXV * 3;       // +120,000

    cudaMemsetAsync(d_out, 0, (size_t)out_size * sizeof(float), 0);

    int nb = (n + CHUNK - 1) / CHUNK;                // 586 for n = 2.4M

    k_init <<<(NVOX + 255) / 256, 256>>>(o_coor);
    k_point<<<(n + 255) / 256, 256>>>(pts, n);
    k_sums <<<nb, 1024>>>(n);
    k_scan <<<1, 1024>>>(nb);
    k_rank <<<nb, 1024>>>(n, o_coor);
    k_emit <<<(MAXV + 7) / 8, 256>>>(pts, (float4*)out, o_np);
}

// round 7
// speedup vs baseline: 2.1825x; 1.3605x over previous
#include <cuda_runtime.h>
#include <cuda_bf16.h>
#include <cstdint>

// ---------------- problem constants ----------------
#define NPMAX   2400000
#define GX      432
#define GY      496
#define NVOX    (GX*GY)        // 214272 (z dim = 1)
#define MAXV    40000
#define MAXP    32
#define CAP     64             // per-voxel bucket capacity (max count ~35, P(>64) ~ e^-60)
#define CHUNK   4096           // points per block in ranking passes
#define SENTINEL 0x7FFFFFFF

// ---------------- device scratch (static: no allocations allowed) ----------------
__device__ int g_first[NVOX];       // min original point index per voxel
__device__ int g_cnt[NVOX];         // total arrivals per voxel
__device__ int g_lin[NPMAX];        // cached voxel id per point (-1 invalid)
__device__ int g_vlist[MAXV];       // slot -> voxel lin id (-1 = unassigned)
__device__ int g_vbuf[NVOX * CAP];  // per-voxel point indices (unordered set)
__device__ int g_bsum[1024];        // per-block first-point counts

// ---------------- voxel coordinate ----------------
// Mirror of what XLA computes for (p - pc_min) / voxel_size: div-by-constant
// rewritten to mul-by-RN(1/const). RN(1/0.16f)=6.25f exactly; RN(1/4)=0.25f.
// Intrinsics block FMA contraction. (Verified bit-exact: rel_err == 0.0.)
__device__ __forceinline__ int point_lin(float4 p) {
    float fx = floorf(__fmul_rn(__fsub_rn(p.x,   0.0f), 6.25f));
    float fy = floorf(__fmul_rn(__fsub_rn(p.y, -39.68f), 6.25f));
    float fz = floorf(__fmul_rn(__fsub_rn(p.z,  -3.0f), 0.25f));
    bool valid = (fx >= 0.f) & (fx < (float)GX) &
                 (fy >= 0.f) & (fy < (float)GY) &
                 (fz >= 0.f) & (fz < 1.f);
    if (!valid) return -1;
    return (int)fy * GX + (int)fx;   // z == 0
}

// ---------------- kernels ----------------
__global__ void k_init(float* __restrict__ o_coor) {
    int i = blockIdx.x * blockDim.x + threadIdx.x;
    if (i < NVOX) { g_first[i] = SENTINEL; g_cnt[i] = 0; }
    if (i < MAXV)  g_vlist[i] = -1;
    if (i < MAXV * 3) o_coor[i] = -1.0f;
}

__global__ void k_point(const float4* __restrict__ pts, int n) {
    int i = blockIdx.x * blockDim.x + threadIdx.x;
    if (i >= n) return;
    int lin = point_lin(pts[i]);
    g_lin[i] = lin;
    if (lin < 0) return;
    atomicMin(&g_first[lin], i);
    int j = atomicAdd(&g_cnt[lin], 1);
    if (j < CAP) g_vbuf[lin * CAP + j] = i;   // unordered set; order fixed later by rank
}

// Per-block count of first-occurrence points. 1024 threads, int4 per thread.
__global__ void k_sums(int n) {
    __shared__ int red[32];
    int tid = threadIdx.x;
    int base = blockIdx.x * CHUNK + tid * 4;
    int s = 0;
    if (base + 3 < n) {
        int4 l4 = *(const int4*)&g_lin[base];
        s += (l4.x >= 0 && g_first[l4.x] == base    ) ? 1 : 0;
        s += (l4.y >= 0 && g_first[l4.y] == base + 1) ? 1 : 0;
        s += (l4.z >= 0 && g_first[l4.z] == base + 2) ? 1 : 0;
        s += (l4.w >= 0 && g_first[l4.w] == base + 3) ? 1 : 0;
    } else {
        for (int k = 0; k < 4; k++) {
            int i = base + k;
            if (i < n) { int l = g_lin[i]; s += (l >= 0 && g_first[l] == i) ? 1 : 0; }
        }
    }
    int lane = tid & 31, w = tid >> 5;
    #pragma unroll
    for (int o = 16; o > 0; o >>= 1) s += __shfl_down_sync(0xffffffffu, s, o);
    if (lane == 0) red[w] = s;
    __syncthreads();
    if (w == 0) {
        int t = red[lane];
        #pragma unroll
        for (int o = 16; o > 0; o >>= 1) t += __shfl_down_sync(0xffffffffu, t, o);
        if (lane == 0) g_bsum[blockIdx.x] = t;
    }
}

// Assign slots. Each block computes its own exclusive offset by reducing
// g_bsum[0..bid) (no separate scan kernel). Blocks past MAXV slots exit.
__global__ void k_rank(int n, int nb, float* __restrict__ o_coor) {
    __shared__ int red[32];
    __shared__ int sh[1024];
    int tid = threadIdx.x;
    int lane = tid & 31, w = tid >> 5;

    // exclusive offset = sum of preceding block counts
    int v = (tid < blockIdx.x) ? g_bsum[tid] : 0;      // nb <= 1024
    #pragma unroll
    for (int o = 16; o > 0; o >>= 1) v += __shfl_down_sync(0xffffffffu, v, o);
    if (lane == 0) red[w] = v;
    __syncthreads();
    if (w == 0) {
        int t = red[lane];
        #pragma unroll
        for (int o = 16; o > 0; o >>= 1) t += __shfl_down_sync(0xffffffffu, t, o);
        if (lane == 0) red[0] = t;
    }
    __syncthreads();
    int off = red[0];
    if (off >= MAXV) return;

    int base = blockIdx.x * CHUNK + tid * 4;
    int lin[4], m[4];
    int s = 0;
    if (base + 3 < n) {
        int4 l4 = *(const int4*)&g_lin[base];
        lin[0] = l4.x; lin[1] = l4.y; lin[2] = l4.z; lin[3] = l4.w;
        #pragma unroll
        for (int k = 0; k < 4; k++) {
            m[k] = (lin[k] >= 0 && g_first[lin[k]] == base + k) ? 1 : 0;
            s += m[k];
        }
    } else {
        #pragma unroll
        for (int k = 0; k < 4; k++) {
            int i = base + k;
            int l = (i < n) ? g_lin[i] : -1;
            lin[k] = l;
            m[k] = (l >= 0 && g_first[l] == i) ? 1 : 0;
            s += m[k];
        }
    }

    sh[tid] = s;
    __syncthreads();
    for (int o = 1; o < 1024; o <<= 1) {
        int t = (tid >= o) ? sh[tid - o] : 0;
        __syncthreads();
        sh[tid] += t;
        __syncthreads();
    }
    int r = off + sh[tid] - s;

    #pragma unroll
    for (int k = 0; k < 4; k++) {
        if (m[k]) {
            if (r < MAXV) {
                g_vlist[r] = lin[k];
                int x = lin[k] % GX, y = lin[k] / GX;   // z == 0
                o_coor[r * 3 + 0] = 0.0f;
                o_coor[r * 3 + 1] = (float)y;
                o_coor[r * 3 + 2] = (float)x;
            }
            r++;
        }
    }
}

// One warp per slot. Ranks bucket entries by original point index (distinct ->
// permutation), writes point rows at their ranks, and ZEROES all padding rows
// itself (no global memset needed):
//   n==0      : all 32 rows zeroed (lanes write row==lane)
//   0<n<=32   : ranks cover [0,n); lanes >= n zero rows [n,32)
//   n>32      : ranks<32 cover all 32 rows exactly
__global__ void k_emit(const float4* __restrict__ pts,
                       float4* __restrict__ o_vox,
                       float* __restrict__ o_np) {
    int s = blockIdx.x * 8 + (threadIdx.x >> 5);
    if (s >= MAXV) return;
    int lane = threadIdx.x & 31;
    int lin = g_vlist[s];
    int n = (lin >= 0) ? g_cnt[lin] : 0;
    if (lane == 0) o_np[s] = (float)min(n, MAXP);
    float4* row = o_vox + (size_t)s * MAXP;
    const float4 z4 = make_float4(0.f, 0.f, 0.f, 0.f);

    if (n <= 32) {                       // common case (incl. empty slots)
        int m = n;
        const int* buf = (lin >= 0) ? &g_vbuf[lin * CAP] : (const int*)0;
        int e0 = (lane < m) ? buf[lane] : SENTINEL;
        int r0 = 0;
        for (int j = 0; j < m; j++) {    // m uniform across the warp
            int a = __shfl_sync(0xffffffffu, e0, j);
            r0 += (a < e0) ? 1 : 0;
        }
        if (lane < m) row[r0] = pts[e0];
        else          row[lane] = z4;    // zero padding rows [m, 32)
    } else {                             // rare: up to 64 entries, keep ranks < 32
        int m = min(n, CAP);
        const int* buf = &g_vbuf[lin * CAP];
        int e0 = (lane      < m) ? buf[lane]      : SENTINEL;
        int e1 = (lane + 32 < m) ? buf[lane + 32] : SENTINEL;
        int r0 = 0, r1 = 0;
        #pragma unroll
        for (int j = 0; j < 32; j++) {
            int a = __shfl_sync(0xffffffffu, e0, j);
            int b = __shfl_sync(0xffffffffu, e1, j);
            r0 += (a < e0) + (b < e0);
            r1 += (a < e1) + (b < e1);
        }
        if (e0 != SENTINEL && r0 < MAXP) row[r0] = pts[e0];
        if (e1 != SENTINEL && r1 < MAXP) row[r1] = pts[e1];
    }
}

// ---------------- launch ----------------
extern "C" void kernel_launch(void* const* d_in, const int* in_sizes, int n_in,
                              void* d_out, int out_size) {
    const float4* pts = (const float4*)d_in[0];
    int n = in_sizes[0] / 4;
    if (n > NPMAX) n = NPMAX;

    float* out    = (float*)d_out;
    float* o_coor = out + (size_t)MAXV * MAXP * 4;   // 5,120,000
    float* o_np   = o_coor + (size_t)MAXV * 3;       // +120,000

    int nb = (n + CHUNK - 1) / CHUNK;                // 586 for n = 2.4M

    k_init <<<(NVOX + 255) / 256, 256>>>(o_coor);
    k_point<<<(n + 255) / 256, 256>>>(pts, n);
    k_sums <<<nb, 1024>>>(n);
    k_rank <<<nb, 1024>>>(n, nb, o_coor);
    k_emit <<<(MAXV + 7) / 8, 256>>>(pts, (float4*)out, o_np);
}

// round 8
// speedup vs baseline: 2.2944x; 1.0513x over previous
#include <cuda_runtime.h>
#include <cuda_bf16.h>
#include <cstdint>

// ---------------- problem constants ----------------
#define NPMAX   2400000
#define GX      432
#define GY      496
#define NVOX    (GX*GY)        // 214272 (z dim = 1)
#define MAXV    40000
#define MAXP    32
#define CAP     64             // per-voxel bucket capacity (max count ~35, P(>64) ~ e^-60)
#define CHUNK   4096           // points per block in the scan kernel
#define SENTINEL 0x7FFFFFFF

#define FLAG_AGG 1ull
#define FLAG_INC 2ull

// ---------------- device scratch (static: no allocations allowed) ----------------
__device__ int g_first[NVOX];                 // min original point index per voxel
__device__ int g_cnt[NVOX];                   // total arrivals per voxel
__device__ int g_lin[NPMAX];                  // cached voxel id per point (-1 invalid)
__device__ int g_vlist[MAXV];                 // slot -> voxel lin id (-1 = unassigned)
__device__ int g_vbuf[NVOX * CAP];            // per-voxel point indices (unordered set)
__device__ unsigned long long g_desc[1024];   // decoupled look-back descriptors

// ---------------- voxel coordinate ----------------
// Mirror of what XLA computes for (p - pc_min) / voxel_size: div-by-constant
// rewritten to mul-by-RN(1/const). RN(1/0.16f)=6.25f exactly; RN(1/4)=0.25f.
// Intrinsics block FMA contraction. (Verified bit-exact: rel_err == 0.0.)
__device__ __forceinline__ int point_lin(float4 p) {
    float fx = floorf(__fmul_rn(__fsub_rn(p.x,   0.0f), 6.25f));
    float fy = floorf(__fmul_rn(__fsub_rn(p.y, -39.68f), 6.25f));
    float fz = floorf(__fmul_rn(__fsub_rn(p.z,  -3.0f), 0.25f));
    bool valid = (fx >= 0.f) & (fx < (float)GX) &
                 (fy >= 0.f) & (fy < (float)GY) &
                 (fz >= 0.f) & (fz < 1.f);
    if (!valid) return -1;
    return (int)fy * GX + (int)fx;   // z == 0
}

__device__ __forceinline__ int warpInclScan(int v, int lane) {
    #pragma unroll
    for (int o = 1; o < 32; o <<= 1) {
        int t = __shfl_up_sync(0xffffffffu, v, o);
        if (lane >= o) v += t;
    }
    return v;
}

// ---------------- kernels ----------------
__global__ void k_init(float* __restrict__ o_coor) {
    int i = blockIdx.x * blockDim.x + threadIdx.x;
    if (i < NVOX) { g_first[i] = SENTINEL; g_cnt[i] = 0; }
    if (i < MAXV)  g_vlist[i] = -1;
    if (i < MAXV * 3) o_coor[i] = -1.0f;
    if (i < 1024)  g_desc[i] = 0ull;
}

__global__ void k_point(const float4* __restrict__ pts, int n) {
    int i = blockIdx.x * blockDim.x + threadIdx.x;
    if (i >= n) return;
    int lin = point_lin(pts[i]);
    g_lin[i] = lin;
    if (lin < 0) return;
    atomicMin(&g_first[lin], i);
    int j = atomicAdd(&g_cnt[lin], 1);
    if (j < CAP) g_vbuf[lin * CAP + j] = i;   // unordered set; order fixed later by rank
}

// Fused count+scan+slot-assignment via decoupled look-back (deterministic:
// produced values are timing-independent). One pass over g_lin, 2 barriers.
__global__ void k_scanrank(int n, float* __restrict__ o_coor) {
    __shared__ int warpTot[32];
    __shared__ int sh_off;
    int tid = threadIdx.x;
    int lane = tid & 31, w = tid >> 5;
    int bid = blockIdx.x;
    int base = bid * CHUNK + tid * 4;

    // ---- marks for 4 consecutive points ----
    int lin[4], m[4];
    int s = 0;
    if (base + 3 < n) {
        int4 l4 = *(const int4*)&g_lin[base];
        lin[0] = l4.x; lin[1] = l4.y; lin[2] = l4.z; lin[3] = l4.w;
        #pragma unroll
        for (int k = 0; k < 4; k++) {
            m[k] = (lin[k] >= 0 && g_first[lin[k]] == base + k) ? 1 : 0;
            s += m[k];
        }
    } else {
        #pragma unroll
        for (int k = 0; k < 4; k++) {
            int i = base + k;
            int l = (i < n) ? g_lin[i] : -1;
            lin[k] = l;
            m[k] = (l >= 0 && g_first[l] == i) ? 1 : 0;
            s += m[k];
        }
    }

    // ---- block scan: warp shfl scan + warp-aggregate scan (2 barriers) ----
    int inc = warpInclScan(s, lane);
    if (lane == 31) warpTot[w] = inc;
    __syncthreads();
    if (w == 0) warpTot[lane] = warpInclScan(warpTot[lane], lane);
    __syncthreads();
    int blockIncl = inc + ((w > 0) ? warpTot[w - 1] : 0);
    int total = warpTot[31];
    int ex = blockIncl - s;          // block-local exclusive prefix

    // ---- decoupled look-back (thread 0) ----
    if (tid == 0) {
        if (bid == 0) {
            atomicExch(&g_desc[0], (FLAG_INC << 32) | (unsigned)total);
            sh_off = 0;
        } else {
            atomicExch(&g_desc[bid], (FLAG_AGG << 32) | (unsigned)total);
            int p = bid - 1;
            int run = 0, off;
            while (true) {
                unsigned long long d = *(volatile unsigned long long*)&g_desc[p];
                unsigned flag = (unsigned)(d >> 32);
                if (flag == (unsigned)FLAG_INC) { off = (int)(unsigned)d + run; break; }
                if (flag == (unsigned)FLAG_AGG) { run += (int)(unsigned)d; p--; }
            }
            atomicExch(&g_desc[bid], (FLAG_INC << 32) | (unsigned)(off + total));
            sh_off = off;
        }
    }
    __syncthreads();
    int off = sh_off;
    if (off >= MAXV) return;         // whole block past the slot budget (~98%)

    int r = off + ex;
    #pragma unroll
    for (int k = 0; k < 4; k++) {
        if (m[k]) {
            if (r < MAXV) {
                g_vlist[r] = lin[k];
                int x = lin[k] % GX, y = lin[k] / GX;   // z == 0
                o_coor[r * 3 + 0] = 0.0f;
                o_coor[r * 3 + 1] = (float)y;
                o_coor[r * 3 + 2] = (float)x;
            }
            r++;
        }
    }
}

// One warp per slot. Ranks bucket entries by original point index (distinct ->
// permutation), writes point rows at their ranks, and ZEROES padding rows
// itself (no global memset):
//   n==0      : all 32 rows zeroed (lanes write row==lane)
//   0<n<=32   : ranks cover [0,n); lanes >= n zero rows [n,32)
//   n>32      : 32 entries have rank < 32 -> all rows rank-written
__global__ void k_emit(const float4* __restrict__ pts,
                       float4* __restrict__ o_vox,
                       float* __restrict__ o_np) {
    int s = blockIdx.x * 8 + (threadIdx.x >> 5);
    if (s >= MAXV) return;
    int lane = threadIdx.x & 31;
    int lin = g_vlist[s];
    int n = (lin >= 0) ? g_cnt[lin] : 0;
    if (lane == 0) o_np[s] = (float)min(n, MAXP);
    float4* row = o_vox + (size_t)s * MAXP;
    const float4 z4 = make_float4(0.f, 0.f, 0.f, 0.f);

    if (n <= 32) {                       // common case (incl. empty slots)
        int m = n;
        const int* buf = (lin >= 0) ? &g_vbuf[lin * CAP] : (const int*)0;
        int e0 = (lane < m) ? buf[lane] : SENTINEL;
        int r0 = 0;
        for (int j = 0; j < m; j++) {    // m uniform across the warp
            int a = __shfl_sync(0xffffffffu, e0, j);
            r0 += (a < e0) ? 1 : 0;
        }
        if (lane < m) row[r0] = pts[e0];
        else          row[lane] = z4;    // zero padding rows [m, 32)
    } else {                             // rare: up to 64 entries, keep ranks < 32
        int m = min(n, CAP);
        const int* buf = &g_vbuf[lin * CAP];
        int e0 = (lane      < m) ? buf[lane]      : SENTINEL;
        int e1 = (lane + 32 < m) ? buf[lane + 32] : SENTINEL;
        int r0 = 0, r1 = 0;
        #pragma unroll
        for (int j = 0; j < 32; j++) {
            int a = __shfl_sync(0xffffffffu, e0, j);
            int b = __shfl_sync(0xffffffffu, e1, j);
            r0 += (a < e0) + (b < e0);
            r1 += (a < e1) + (b < e1);
        }
        if (e0 != SENTINEL && r0 < MAXP) row[r0] = pts[e0];
        if (e1 != SENTINEL && r1 < MAXP) row[r1] = pts[e1];
    }
}

// ---------------- launch ----------------
extern "C" void kernel_launch(void* const* d_in, const int* in_sizes, int n_in,
                              void* d_out, int out_size) {
    const float4* pts = (const float4*)d_in[0];
    int n = in_sizes[0] / 4;
    if (n > NPMAX) n = NPMAX;

    float* out    = (float*)d_out;
    float* o_coor = out + (size_t)MAXV * MAXP * 4;   // 5,120,000
    float* o_np   = o_coor + (size_t)MAXV * 3;       // +120,000

    int nb = (n + CHUNK - 1) / CHUNK;                // 586 for n = 2.4M

    k_init    <<<(NVOX + 255) / 256, 256>>>(o_coor);
    k_point   <<<(n + 255) / 256, 256>>>(pts, n);
    k_scanrank<<<nb, 1024>>>(n, o_coor);
    k_emit    <<<(MAXV + 7) / 8, 256>>>(pts, (float4*)out, o_np);
}